// round 7
// baseline (speedup 1.0000x reference)
#include <cuda_runtime.h>
#include <cstdint>

// Shapes: x[256,100,512] f32, W1[1024,512] f32, b1[1024], W2[8,1024], b2[8]
// out[256,8] f32.
#define T_STEPS 100
#define B_SZ    256
#define IN_F    512
#define HID     1024
#define CLS     8
#define M_TOTAL (B_SZ * T_STEPS)   // 25600

// ---------------- device scratch (static; no allocations) -----------------
// int8 limb arrays, radix 128:  a = 2^-4 * (A0 + A1/128 + A2/128^2 + A3/128^3)
//                               w = 2^-11 * (B0 + B1/128 + B2/128^2 + B3/128^3)
__device__ float g_cur[(size_t)M_TOTAL * HID];            // 104.9 MB
__device__ __align__(16) char g_Aq[(size_t)M_TOTAL * 2048]; // [m][limb0..3 x 512]
__device__ __align__(16) char g_Bq[(size_t)HID * 2048];     // [n][limb0..3 x 512]

// ---------------- base-PTX helpers (sm_80+) --------------------------------
__device__ __forceinline__ uint32_t smem_u32(const void* p) {
    uint32_t a;
    asm("{ .reg .u64 t; cvta.to.shared.u64 t, %1; cvt.u32.u64 %0, t; }" : "=r"(a) : "l"(p));
    return a;
}
__device__ __forceinline__ void cp16(uint32_t dst, const void* src) {
    asm volatile("cp.async.cg.shared.global [%0], [%1], 16;" :: "r"(dst), "l"(src));
}
#define CP_COMMIT() asm volatile("cp.async.commit_group;")
#define CP_WAIT(n)  asm volatile("cp.async.wait_group %0;" :: "n"(n))

__device__ __forceinline__ void ldm_x4(uint32_t* r, uint32_t addr) {
    asm volatile("ldmatrix.sync.aligned.m8n8.x4.shared.b16 {%0,%1,%2,%3}, [%4];"
        : "=r"(r[0]), "=r"(r[1]), "=r"(r[2]), "=r"(r[3]) : "r"(addr));
}
// s8 IMMA, s32 accumulate. Integer accumulation is EXACT -> full chaining OK.
__device__ __forceinline__ void imma_acc(int* d, const uint32_t* a,
                                         uint32_t b0, uint32_t b1) {
    asm volatile("mma.sync.aligned.m16n8k32.row.col.s32.s8.s8.s32 "
        "{%0,%1,%2,%3}, {%4,%5,%6,%7}, {%8,%9}, {%0,%1,%2,%3};"
        : "+r"(d[0]), "+r"(d[1]), "+r"(d[2]), "+r"(d[3])
        : "r"(a[0]), "r"(a[1]), "r"(a[2]), "r"(a[3]), "r"(b0), "r"(b1));
}
__device__ __forceinline__ void imma_zero(int* d, const uint32_t* a,
                                          uint32_t b0, uint32_t b1) {
    asm volatile("mma.sync.aligned.m16n8k32.row.col.s32.s8.s8.s32 "
        "{%0,%1,%2,%3}, {%4,%5,%6,%7}, {%8,%9}, {%10,%10,%10,%10};"
        : "=r"(d[0]), "=r"(d[1]), "=r"(d[2]), "=r"(d[3])
        : "r"(a[0]), "r"(a[1]), "r"(a[2]), "r"(a[3]), "r"(b0), "r"(b1),
          "r"(0));
}

// ---------------- Kernel A: fp32 -> 4 x int8 limbs -------------------------
// All extraction steps are exact in fp32 (power-of-2 scales, Sterbenz subs).
__device__ __forceinline__ void quant_store(char* base, size_t row, int col,
                                            const float* vv, float scale) {
    char q[4][4];
    #pragma unroll
    for (int j = 0; j < 4; j++) {
        float v = vv[j] * scale;
        float q0 = fminf(fmaxf(rintf(v), -127.f), 127.f);
        float r1 = (v - q0) * 128.0f;
        float q1 = fminf(fmaxf(rintf(r1), -127.f), 127.f);
        float r2 = (r1 - q1) * 128.0f;
        float q2 = fminf(fmaxf(rintf(r2), -127.f), 127.f);
        float r3 = (r2 - q2) * 128.0f;
        float q3 = fminf(fmaxf(rintf(r3), -127.f), 127.f);
        q[0][j] = (char)(int)q0; q[1][j] = (char)(int)q1;
        q[2][j] = (char)(int)q2; q[3][j] = (char)(int)q3;
    }
    #pragma unroll
    for (int L = 0; L < 4; L++)
        *reinterpret_cast<char4*>(&base[row * 2048 + L * 512 + col]) =
            make_char4(q[L][0], q[L][1], q[L][2], q[L][3]);
}
__global__ void convert_x(const float* __restrict__ x) {
    size_t i = (size_t)blockIdx.x * blockDim.x + threadIdx.x;   // one float4
    float4 v = reinterpret_cast<const float4*>(x)[i];
    size_t f = i * 4;
    float vv[4] = {v.x, v.y, v.z, v.w};
    quant_store(g_Aq, f >> 9, (int)(f & 511), vv, 16.0f);       // sA = 2^-4
}
__global__ void convert_w(const float* __restrict__ w) {
    size_t i = (size_t)blockIdx.x * blockDim.x + threadIdx.x;
    float4 v = reinterpret_cast<const float4*>(w)[i];
    size_t f = i * 4;
    float vv[4] = {v.x, v.y, v.z, v.w};
    quant_store(g_Bq, f >> 9, (int)(f & 511), vv, 2048.0f);     // sB = 2^-11
}

// ---------------- GEMM: int8 IMMA, grouped limb products -------------------
// Products (i,j) with i+j<=3, grouped by weight 2^-7(i+j), ordered g3->g0.
// Each group chains exactly through the s32 TC accumulator; group partials
// combine via Horner in SMEM:  F = F*2^-7 + (float)S.
// CTA tile 128(m) x 128(n); 8 warps 2(m) x 4(n); warp tile 64x32.
// Chunk = 128 int8 k-cols = 128 B/row; double-buffered cp.async (R6 geometry).
__constant__ int2 LIMB_BLK[10] = {
    {0,3},{1,2},{2,1},{3,0},   // g3: chunks 0..15
    {0,2},{1,1},{2,0},         // g2: chunks 16..27
    {0,1},{1,0},               // g1: chunks 28..35
    {0,0},                     // g0: chunks 36..39
};
#define NCHUNKS 40
#define SMEM_STAGES 65536                       // A 2x16KB + B 2x16KB
#define ACCF_STRIDE 132
#define SMEM_BYTES (SMEM_STAGES + 128 * ACCF_STRIDE * 4)   // +67584 = 133120

__device__ __forceinline__ void load_chunk(int c, uint32_t sAst, uint32_t sBst,
                                           int tid, int mbase, int nbase) {
    const int2 lb = LIMB_BLK[c >> 2];
    const int kk = (c & 3) * 128;
    const int a_off = lb.x * 512 + kk;
    const int b_off = lb.y * 512 + kk;
    #pragma unroll
    for (int p = 0; p < 4; p++) {            // A: 128 rows x 128B
        const int o   = tid + p * 256;
        const int row = o >> 3;
        const int q   = o & 7;
        const uint32_t dst = sAst + row * 128 + ((q * 16) ^ ((row & 7) << 4));
        cp16(dst, &g_Aq[(size_t)(mbase + row) * 2048 + a_off + q * 16]);
    }
    #pragma unroll
    for (int p = 0; p < 4; p++) {            // B: 128 rows x 128B
        const int o   = tid + p * 256;
        const int row = o >> 3;
        const int q   = o & 7;
        const uint32_t dst = sBst + row * 128 + ((q * 16) ^ ((row & 7) << 4));
        cp16(dst, &g_Bq[(size_t)(nbase + row) * 2048 + b_off + q * 16]);
    }
    CP_COMMIT();
}

__global__ __launch_bounds__(256, 1)
void gemm_fc1_imma(const float* __restrict__ b1) {
    extern __shared__ char smem[];
    const uint32_t sb = smem_u32(smem);
    const int tid  = threadIdx.x;
    const int lane = tid & 31;
    const int wid  = tid >> 5;
    const int wm   = wid >> 2;         // 0..1 (m)
    const int wn   = wid & 3;          // 0..3 (n)
    const int mbase = blockIdx.y * 128;
    const int nbase = blockIdx.x * 128;

    const uint32_t sA[2] = {sb, sb + 16384};
    const uint32_t sB[2] = {sb + 32768, sb + 49152};
    float* accf = reinterpret_cast<float*>(smem + SMEM_STAGES);

    int acc[4][4][4];                  // [mm][bg][e], s32, TC-chained per group

    const int lrow  = lane & 15;
    const int lhalf = (lane >> 4) * 16;

    load_chunk(0, sA[0], sB[0], tid, mbase, nbase);

    for (int c = 0; c < NCHUNKS; c++) {
        const int st = c & 1;
        if (c < NCHUNKS - 1) {
            load_chunk(c + 1, sA[st ^ 1], sB[st ^ 1], tid, mbase, nbase);
            CP_WAIT(1);
        } else {
            CP_WAIT(0);
        }
        __syncthreads();

        const bool group_start = (c == 0 || c == 16 || c == 28 || c == 36);
        #pragma unroll
        for (int ks = 0; ks < 4; ks++) {
            const int cb = ks * 32 + lhalf;
            uint32_t a[4][4], b0q[4], b1q[4];
            #pragma unroll
            for (int mm = 0; mm < 4; mm++) {
                const int row = wm * 64 + mm * 16 + lrow;
                ldm_x4(a[mm], sA[st] + row * 128 + (cb ^ ((row & 7) << 4)));
            }
            {
                const int r0 = wn * 32 + lrow;
                ldm_x4(b0q, sB[st] + r0 * 128 + (cb ^ ((r0 & 7) << 4)));
                const int r1 = wn * 32 + 16 + lrow;
                ldm_x4(b1q, sB[st] + r1 * 128 + (cb ^ ((r1 & 7) << 4)));
            }
            #pragma unroll
            for (int mm = 0; mm < 4; mm++) {
                if (group_start && ks == 0) {
                    imma_zero(acc[mm][0], a[mm], b0q[0], b0q[2]);
                    imma_zero(acc[mm][1], a[mm], b0q[1], b0q[3]);
                    imma_zero(acc[mm][2], a[mm], b1q[0], b1q[2]);
                    imma_zero(acc[mm][3], a[mm], b1q[1], b1q[3]);
                } else {
                    imma_acc(acc[mm][0], a[mm], b0q[0], b0q[2]);
                    imma_acc(acc[mm][1], a[mm], b0q[1], b0q[3]);
                    imma_acc(acc[mm][2], a[mm], b1q[0], b1q[2]);
                    imma_acc(acc[mm][3], a[mm], b1q[1], b1q[3]);
                }
            }
        }
        __syncthreads();

        // Horner group boundaries (each thread touches only its own cells)
        if (c == 15) {
            #pragma unroll
            for (int mm = 0; mm < 4; mm++)
                #pragma unroll
                for (int bg = 0; bg < 4; bg++)
                    #pragma unroll
                    for (int e = 0; e < 4; e++) {
                        const int r = wm * 64 + mm * 16 + (lane >> 2) + (e >> 1) * 8;
                        const int col = wn * 32 + bg * 8 + (lane & 3) * 2 + (e & 1);
                        accf[r * ACCF_STRIDE + col] = (float)acc[mm][bg][e];
                    }
        } else if (c == 27 || c == 35) {
            #pragma unroll
            for (int mm = 0; mm < 4; mm++)
                #pragma unroll
                for (int bg = 0; bg < 4; bg++)
                    #pragma unroll
                    for (int e = 0; e < 4; e++) {
                        const int r = wm * 64 + mm * 16 + (lane >> 2) + (e >> 1) * 8;
                        const int col = wn * 32 + bg * 8 + (lane & 3) * 2 + (e & 1);
                        float f = accf[r * ACCF_STRIDE + col];
                        accf[r * ACCF_STRIDE + col] =
                            fmaf(f, 0.0078125f, (float)acc[mm][bg][e]);
                    }
        }
    }

    // Final: F = accf*2^-7 + S0;  cur = F * 2^-15 + b1[n]
    #pragma unroll
    for (int mm = 0; mm < 4; mm++)
        #pragma unroll
        for (int bg = 0; bg < 4; bg++) {
            const int r   = wm * 64 + mm * 16 + (lane >> 2);
            const int col = wn * 32 + bg * 8 + (lane & 3) * 2;
            #pragma unroll
            for (int half = 0; half < 2; half++) {
                const int rr = r + half * 8;
                float f0 = accf[rr * ACCF_STRIDE + col];
                float f1 = accf[rr * ACCF_STRIDE + col + 1];
                float F0 = fmaf(f0, 0.0078125f, (float)acc[mm][bg][half * 2]);
                float F1 = fmaf(f1, 0.0078125f, (float)acc[mm][bg][half * 2 + 1]);
                const int n = nbase + col;
                float2 v = make_float2(
                    fmaf(F0, 3.0517578125e-05f, b1[n]),
                    fmaf(F1, 3.0517578125e-05f, b1[n + 1]));
                *reinterpret_cast<float2*>(
                    &g_cur[(size_t)(mbase + rr) * 1024 + n]) = v;
            }
        }
}

// ---------------- Kernel C: LIF scan + fused output GEMM ------------------
__global__ __launch_bounds__(1024, 1)
void lif_reduce(const float* __restrict__ W2, const float* __restrict__ b2,
                float* __restrict__ out) {
    const int b = blockIdx.x;
    const int h = threadIdx.x;
    const float* p = g_cur + (size_t)b * T_STEPS * HID + h;

    float mem = 0.0f, spk_sum = 0.0f;
    #pragma unroll 4
    for (int t = 0; t < T_STEPS; t++) {
        const float c = p[t * HID];
        const float reset = (mem > 1.0f) ? 1.0f : 0.0f;
        mem = 0.9f * mem + c - reset;
        spk_sum += (mem > 1.0f) ? 1.0f : 0.0f;
    }
    float part[8];
    #pragma unroll
    for (int c = 0; c < 8; c++) part[c] = spk_sum * W2[c * HID + h];
    #pragma unroll
    for (int c = 0; c < 8; c++)
        #pragma unroll
        for (int o = 16; o > 0; o >>= 1)
            part[c] += __shfl_down_sync(0xffffffffu, part[c], o);

    __shared__ float s_red[8][32];
    const int lane = h & 31, warp = h >> 5;
    if (lane == 0)
        #pragma unroll
        for (int c = 0; c < 8; c++) s_red[c][warp] = part[c];
    __syncthreads();
    if (threadIdx.x < 256) {
        const int c = threadIdx.x >> 5, w = threadIdx.x & 31;
        float v = s_red[c][w];
        #pragma unroll
        for (int o = 16; o > 0; o >>= 1)
            v += __shfl_down_sync(0xffffffffu, v, o);
        if (w == 0) out[b * CLS + c] = v + 100.0f * b2[c];
    }
}

// ---------------------------------------------------------------------------
extern "C" void kernel_launch(void* const* d_in, const int* in_sizes, int n_in,
                              void* d_out, int out_size) {
    const float* x  = (const float*)d_in[0];
    const float* W1 = (const float*)d_in[1];
    const float* b1 = (const float*)d_in[2];
    const float* W2 = (const float*)d_in[3];
    const float* b2 = (const float*)d_in[4];
    float* out = (float*)d_out;

    cudaFuncSetAttribute(gemm_fc1_imma,
                         cudaFuncAttributeMaxDynamicSharedMemorySize, SMEM_BYTES);

    convert_x<<<(M_TOTAL * IN_F / 4) / 256, 256>>>(x);   // 12800 blocks
    convert_w<<<(HID * IN_F / 4) / 256, 256>>>(W1);      // 512 blocks
    // grid: x = n-tiles (8) fastest -> CTAs sharing an A chunk co-scheduled
    gemm_fc1_imma<<<dim3(HID / 128, M_TOTAL / 128), 256, SMEM_BYTES>>>(b1);
    lif_reduce<<<B_SZ, 1024>>>(W2, b2, out);
}

// round 8
// speedup vs baseline: 3.1132x; 3.1132x over previous
#include <cuda_runtime.h>
#include <cuda_bf16.h>
#include <cstdint>

// Shapes: x[256,100,512] f32, W1[1024,512] f32, b1[1024], W2[8,1024], b2[8]
// out[256,8] f32.
#define T_STEPS 100
#define B_SZ    256
#define IN_F    512
#define HID     1024
#define CLS     8
#define M_TOTAL (B_SZ * T_STEPS)   // 25600
#define KW      1536               // 3 bf16 terms x 512

// ---------------- device scratch (static; no allocations) -----------------
__device__ float         g_cur[(size_t)M_TOTAL * HID];   // 104.9 MB
__device__ __nv_bfloat16 g_A2[(size_t)M_TOTAL * KW];     // [m][a0|a1|a2] 78.6 MB
__device__ __nv_bfloat16 g_B2[(size_t)HID * KW];         // [n][b0|b1|b2]  3.1 MB

// ---------------- base-PTX helpers (sm_80+) --------------------------------
__device__ __forceinline__ uint32_t smem_u32(const void* p) {
    uint32_t a;
    asm("{ .reg .u64 t; cvta.to.shared.u64 t, %1; cvt.u32.u64 %0, t; }" : "=r"(a) : "l"(p));
    return a;
}
__device__ __forceinline__ void cp16(uint32_t dst, const void* src) {
    asm volatile("cp.async.cg.shared.global [%0], [%1], 16;" :: "r"(dst), "l"(src));
}
#define CP_COMMIT() asm volatile("cp.async.commit_group;")
#define CP_WAIT(n)  asm volatile("cp.async.wait_group %0;" :: "n"(n))

__device__ __forceinline__ void ldm_x4(uint32_t* r, uint32_t addr) {
    asm volatile("ldmatrix.sync.aligned.m8n8.x4.shared.b16 {%0,%1,%2,%3}, [%4];"
        : "=r"(r[0]), "=r"(r[1]), "=r"(r[2]), "=r"(r[3]) : "r"(addr));
}
// Chained mma: D += A*B through the TC accumulator (RZ-biased add; only safe
// when |acc| is small -- used for the 2^-8-scale segments).
__device__ __forceinline__ void mma_chain(float* c, const uint32_t* a,
                                          uint32_t b0, uint32_t b1) {
    asm volatile("mma.sync.aligned.m16n8k16.row.col.f32.bf16.bf16.f32 "
        "{%0,%1,%2,%3}, {%4,%5,%6,%7}, {%8,%9}, {%0,%1,%2,%3};"
        : "+f"(c[0]), "+f"(c[1]), "+f"(c[2]), "+f"(c[3])
        : "r"(a[0]), "r"(a[1]), "r"(a[2]), "r"(a[3]), "r"(b0), "r"(b1));
}
// Isolated start: D = A*B + 0.
__device__ __forceinline__ void mma_zero(float* d, const uint32_t* a,
                                         uint32_t b0, uint32_t b1) {
    asm volatile("mma.sync.aligned.m16n8k16.row.col.f32.bf16.bf16.f32 "
        "{%0,%1,%2,%3}, {%4,%5,%6,%7}, {%8,%9}, {%10,%10,%10,%10};"
        : "=f"(d[0]), "=f"(d[1]), "=f"(d[2]), "=f"(d[3])
        : "r"(a[0]), "r"(a[1]), "r"(a[2]), "r"(a[3]), "r"(b0), "r"(b1),
          "f"(0.0f));
}

// ---------------- Kernel A: fp32 -> 3-way bf16 split ----------------------
__device__ __forceinline__ void split3_store(__nv_bfloat16* base, size_t row,
                                             int col, const float* vv) {
    __align__(8) __nv_bfloat16 t0[4], t1[4], t2[4];
    #pragma unroll
    for (int j = 0; j < 4; j++) {
        const float a = vv[j];
        t0[j] = __float2bfloat16_rn(a);
        const float r1 = a - __bfloat162float(t0[j]);
        t1[j] = __float2bfloat16_rn(r1);
        t2[j] = __float2bfloat16_rn(r1 - __bfloat162float(t1[j]));
    }
    *reinterpret_cast<uint2*>(&base[row * KW + col])        = *reinterpret_cast<uint2*>(t0);
    *reinterpret_cast<uint2*>(&base[row * KW + 512 + col])  = *reinterpret_cast<uint2*>(t1);
    *reinterpret_cast<uint2*>(&base[row * KW + 1024 + col]) = *reinterpret_cast<uint2*>(t2);
}
__global__ void convert_x(const float* __restrict__ x) {
    size_t i = (size_t)blockIdx.x * blockDim.x + threadIdx.x;   // one float4
    float4 v = reinterpret_cast<const float4*>(x)[i];
    size_t f = i * 4;
    float vv[4] = {v.x, v.y, v.z, v.w};
    split3_store(g_A2, f >> 9, (int)(f & 511), vv);
}
__global__ void convert_w(const float* __restrict__ w) {
    size_t i = (size_t)blockIdx.x * blockDim.x + threadIdx.x;
    float4 v = reinterpret_cast<const float4*>(w)[i];
    size_t f = i * 4;
    float vv[4] = {v.x, v.y, v.z, v.w};
    split3_store(g_B2, f >> 9, (int)(f & 511), vv);
}

// ---------------- GEMM helpers --------------------------------------------
// Segment order: the 5 SMALL products first (chunks 0..39, fully TC-chained;
// their natural limb magnitudes keep |acc| <= ~2^-8 so the RZ bias is ~3e-8),
// then a0*b0 last (chunks 40..47, pair-chained + fp32 FADD fold).
__constant__ int2 SEG_COLS[6] = {
    {0, 512},     // a0*b1   (2^-8)
    {512, 0},     // a1*b0   (2^-8)
    {0, 1024},    // a0*b2   (2^-16)
    {512, 512},   // a1*b1   (2^-16)
    {1024, 0},    // a2*b0   (2^-16)
    {0, 0},       // a0*b0   (1)  -- phase 2
};
#define NCHUNKS 48
#define SMEM_BYTES 98304

__device__ __forceinline__ void load_chunk(int c, uint32_t sAst, uint32_t sBst,
                                           int tid, int mbase, int nbase) {
    const int2 sc = SEG_COLS[c >> 3];
    const int kk = (c & 7) * 64;
    const int a_col = sc.x + kk;
    const int b_col = sc.y + kk;
    #pragma unroll
    for (int p = 0; p < 4; p++) {            // A: 128 rows x 128B
        const int o   = tid + p * 256;
        const int row = o >> 3;
        const int q   = o & 7;
        const uint32_t dst = sAst + row * 128 + ((q * 16) ^ ((row & 7) << 4));
        cp16(dst, &g_A2[(size_t)(mbase + row) * KW + a_col + q * 8]);
    }
    #pragma unroll
    for (int p = 0; p < 8; p++) {            // B: 256 rows x 128B
        const int o   = tid + p * 256;
        const int row = o >> 3;
        const int q   = o & 7;
        const uint32_t dst = sBst + row * 128 + ((q * 16) ^ ((row & 7) << 4));
        cp16(dst, &g_B2[(size_t)(nbase + row) * KW + b_col + q * 8]);
    }
    CP_COMMIT();
}

// ---------------- Kernel B: mma.sync bf16 GEMM, bias-controlled chaining ---
// CTA tile 128(m) x 256(n); 8 warps 2x4; warp tile 64x64; double-buffered.
__global__ __launch_bounds__(256, 1)
void gemm_fc1_mma(const float* __restrict__ b1) {
    extern __shared__ char smem[];
    const uint32_t sb = smem_u32(smem);
    const int tid  = threadIdx.x;
    const int lane = tid & 31;
    const int wid  = tid >> 5;
    const int wm   = wid >> 2;         // 0..1  (m)
    const int wn   = wid & 3;          // 0..3  (n)
    const int mbase = blockIdx.y * 128;
    const int nbase = blockIdx.x * 256;

    const uint32_t sA[2] = {sb, sb + 16384};
    const uint32_t sB[2] = {sb + 32768, sb + 65536};

    float acc[4][8][4];                // doubles as phase-1 TC chain registers

    const int lrow  = lane & 15;
    const int lhalf = (lane >> 4) * 16;

    load_chunk(0, sA[0], sB[0], tid, mbase, nbase);

    for (int c = 0; c < NCHUNKS; c++) {
        const int st = c & 1;
        if (c < NCHUNKS - 1) {
            load_chunk(c + 1, sA[st ^ 1], sB[st ^ 1], tid, mbase, nbase);
            CP_WAIT(1);
        } else {
            CP_WAIT(0);
        }
        __syncthreads();

        if (c < 40) {
            // Phase 1: small segments, fully chained through the TC.
            #pragma unroll
            for (int ks = 0; ks < 4; ks++) {
                const int cb = ks * 32 + lhalf;
                uint32_t a[4][4], b[4][4];
                #pragma unroll
                for (int mm = 0; mm < 4; mm++) {
                    const int row = wm * 64 + mm * 16 + lrow;
                    ldm_x4(a[mm], sA[st] + row * 128 + (cb ^ ((row & 7) << 4)));
                }
                #pragma unroll
                for (int bq = 0; bq < 4; bq++) {
                    const int row = wn * 64 + bq * 16 + lrow;
                    ldm_x4(b[bq], sB[st] + row * 128 + (cb ^ ((row & 7) << 4)));
                }
                if (c == 0 && ks == 0) {
                    #pragma unroll
                    for (int mm = 0; mm < 4; mm++)
                        #pragma unroll
                        for (int bq = 0; bq < 4; bq++) {
                            mma_zero(acc[mm][bq * 2],     a[mm], b[bq][0], b[bq][2]);
                            mma_zero(acc[mm][bq * 2 + 1], a[mm], b[bq][1], b[bq][3]);
                        }
                } else {
                    #pragma unroll
                    for (int mm = 0; mm < 4; mm++)
                        #pragma unroll
                        for (int bq = 0; bq < 4; bq++) {
                            mma_chain(acc[mm][bq * 2],     a[mm], b[bq][0], b[bq][2]);
                            mma_chain(acc[mm][bq * 2 + 1], a[mm], b[bq][1], b[bq][3]);
                        }
                }
            }
        } else {
            // Phase 2: a0*b0. Pair-chain (k=32, |partial| small) then fold
            // with fp32 RN FADD into acc.
            #pragma unroll
            for (int kp = 0; kp < 2; kp++) {
                uint32_t a[2][4][4], b[2][4][4];
                #pragma unroll
                for (int half = 0; half < 2; half++) {
                    const int cb = (kp * 2 + half) * 32 + lhalf;
                    #pragma unroll
                    for (int mm = 0; mm < 4; mm++) {
                        const int row = wm * 64 + mm * 16 + lrow;
                        ldm_x4(a[half][mm],
                               sA[st] + row * 128 + (cb ^ ((row & 7) << 4)));
                    }
                    #pragma unroll
                    for (int bq = 0; bq < 4; bq++) {
                        const int row = wn * 64 + bq * 16 + lrow;
                        ldm_x4(b[half][bq],
                               sB[st] + row * 128 + (cb ^ ((row & 7) << 4)));
                    }
                }
                #pragma unroll
                for (int mm = 0; mm < 4; mm++)
                    #pragma unroll
                    for (int bq = 0; bq < 4; bq++) {
                        float t0[4], t1[4];
                        mma_zero (t0, a[0][mm], b[0][bq][0], b[0][bq][2]);
                        mma_chain(t0, a[1][mm], b[1][bq][0], b[1][bq][2]);
                        mma_zero (t1, a[0][mm], b[0][bq][1], b[0][bq][3]);
                        mma_chain(t1, a[1][mm], b[1][bq][1], b[1][bq][3]);
                        #pragma unroll
                        for (int e = 0; e < 4; e++) {
                            acc[mm][bq * 2][e]     += t0[e];
                            acc[mm][bq * 2 + 1][e] += t1[e];
                        }
                    }
            }
        }
        __syncthreads();
    }

    // Epilogue: bias + store f32 to g_cur.
    const int qrow = lane >> 2;            // 0..7
    const int qcol = (lane & 3) * 2;       // 0,2,4,6
    #pragma unroll
    for (int bqn = 0; bqn < 8; bqn++) {
        const int n = nbase + wn * 64 + bqn * 8 + qcol;
        const float bv0 = b1[n], bv1 = b1[n + 1];
        #pragma unroll
        for (int mm = 0; mm < 4; mm++) {
            const int r0 = mbase + wm * 64 + mm * 16 + qrow;
            float2 v0 = make_float2(acc[mm][bqn][0] + bv0, acc[mm][bqn][1] + bv1);
            float2 v1 = make_float2(acc[mm][bqn][2] + bv0, acc[mm][bqn][3] + bv1);
            *reinterpret_cast<float2*>(&g_cur[(size_t)r0 * 1024 + n])       = v0;
            *reinterpret_cast<float2*>(&g_cur[(size_t)(r0 + 8) * 1024 + n]) = v1;
        }
    }
}

// ---------------- Kernel C: LIF scan + fused output GEMM ------------------
__global__ __launch_bounds__(1024, 1)
void lif_reduce(const float* __restrict__ W2, const float* __restrict__ b2,
                float* __restrict__ out) {
    const int b = blockIdx.x;
    const int h = threadIdx.x;
    const float* p = g_cur + (size_t)b * T_STEPS * HID + h;

    float mem = 0.0f, spk_sum = 0.0f;
    #pragma unroll 4
    for (int t = 0; t < T_STEPS; t++) {
        const float c = p[t * HID];
        const float reset = (mem > 1.0f) ? 1.0f : 0.0f;
        mem = 0.9f * mem + c - reset;
        spk_sum += (mem > 1.0f) ? 1.0f : 0.0f;
    }
    float part[8];
    #pragma unroll
    for (int c = 0; c < 8; c++) part[c] = spk_sum * W2[c * HID + h];
    #pragma unroll
    for (int c = 0; c < 8; c++)
        #pragma unroll
        for (int o = 16; o > 0; o >>= 1)
            part[c] += __shfl_down_sync(0xffffffffu, part[c], o);

    __shared__ float s_red[8][32];
    const int lane = h & 31, warp = h >> 5;
    if (lane == 0)
        #pragma unroll
        for (int c = 0; c < 8; c++) s_red[c][warp] = part[c];
    __syncthreads();
    if (threadIdx.x < 256) {
        const int c = threadIdx.x >> 5, w = threadIdx.x & 31;
        float v = s_red[c][w];
        #pragma unroll
        for (int o = 16; o > 0; o >>= 1)
            v += __shfl_down_sync(0xffffffffu, v, o);
        if (w == 0) out[b * CLS + c] = v + 100.0f * b2[c];
    }
}

// ---------------------------------------------------------------------------
extern "C" void kernel_launch(void* const* d_in, const int* in_sizes, int n_in,
                              void* d_out, int out_size) {
    const float* x  = (const float*)d_in[0];
    const float* W1 = (const float*)d_in[1];
    const float* b1 = (const float*)d_in[2];
    const float* W2 = (const float*)d_in[3];
    const float* b2 = (const float*)d_in[4];
    float* out = (float*)d_out;

    cudaFuncSetAttribute(gemm_fc1_mma, cudaFuncAttributeMaxDynamicSharedMemorySize,
                         SMEM_BYTES);

    convert_x<<<(M_TOTAL * IN_F / 4) / 256, 256>>>(x);   // 12800 blocks
    convert_w<<<(HID * IN_F / 4) / 256, 256>>>(W1);      // 512 blocks
    // grid: x = n-blocks (4) fastest -> CTAs sharing an A chunk co-scheduled
    gemm_fc1_mma<<<dim3(HID / 256, M_TOTAL / 128), 256, SMEM_BYTES>>>(b1);
    lif_reduce<<<B_SZ, 1024>>>(W2, b2, out);
}

// round 9
// speedup vs baseline: 5.5546x; 1.7842x over previous
#include <cuda_runtime.h>
#include <cuda_fp16.h>
#include <cstdint>

// Shapes: x[256,100,512] f32, W1[1024,512] f32, b1[1024], W2[8,1024], b2[8]
// out[256,8] f32.
#define T_STEPS 100
#define B_SZ    256
#define IN_F    512
#define HID     1024
#define CLS     8
#define M_TOTAL (B_SZ * T_STEPS)   // 25600
#define KW      1024               // 2 fp16 terms x 512

// ---------------- device scratch (static; no allocations) -----------------
__device__ float  g_cur[(size_t)M_TOTAL * HID];   // 104.9 MB
__device__ __half g_A2[(size_t)M_TOTAL * KW];     // [m][a0|a1] 52.4 MB
__device__ __half g_B2[(size_t)HID * KW];         // [n][b0|b1]  2.1 MB

// ---------------- base-PTX helpers (sm_80+) --------------------------------
__device__ __forceinline__ uint32_t smem_u32(const void* p) {
    uint32_t a;
    asm("{ .reg .u64 t; cvta.to.shared.u64 t, %1; cvt.u32.u64 %0, t; }" : "=r"(a) : "l"(p));
    return a;
}
__device__ __forceinline__ void cp16(uint32_t dst, const void* src) {
    asm volatile("cp.async.cg.shared.global [%0], [%1], 16;" :: "r"(dst), "l"(src));
}
#define CP_COMMIT() asm volatile("cp.async.commit_group;")
#define CP_WAIT(n)  asm volatile("cp.async.wait_group %0;" :: "n"(n))

__device__ __forceinline__ void ldm_x4(uint32_t* r, uint32_t addr) {
    asm volatile("ldmatrix.sync.aligned.m8n8.x4.shared.b16 {%0,%1,%2,%3}, [%4];"
        : "=r"(r[0]), "=r"(r[1]), "=r"(r[2]), "=r"(r[3]) : "r"(addr));
}
// Chained mma: D += A*B through the TC accumulator (RZ-biased add; safe only
// while |acc| stays small -- used for the 2^-11-scale segments + k32 pairs).
__device__ __forceinline__ void mma_chain(float* c, const uint32_t* a,
                                          uint32_t b0, uint32_t b1) {
    asm volatile("mma.sync.aligned.m16n8k16.row.col.f32.f16.f16.f32 "
        "{%0,%1,%2,%3}, {%4,%5,%6,%7}, {%8,%9}, {%0,%1,%2,%3};"
        : "+f"(c[0]), "+f"(c[1]), "+f"(c[2]), "+f"(c[3])
        : "r"(a[0]), "r"(a[1]), "r"(a[2]), "r"(a[3]), "r"(b0), "r"(b1));
}
// Isolated start: D = A*B + 0.
__device__ __forceinline__ void mma_zero(float* d, const uint32_t* a,
                                         uint32_t b0, uint32_t b1) {
    asm volatile("mma.sync.aligned.m16n8k16.row.col.f32.f16.f16.f32 "
        "{%0,%1,%2,%3}, {%4,%5,%6,%7}, {%8,%9}, {%10,%10,%10,%10};"
        : "=f"(d[0]), "=f"(d[1]), "=f"(d[2]), "=f"(d[3])
        : "r"(a[0]), "r"(a[1]), "r"(a[2]), "r"(a[3]), "r"(b0), "r"(b1),
          "f"(0.0f));
}

// ---------------- Kernel A: fp32 -> 2-way fp16 split ----------------------
// a0 = fp16(a); a1 = fp16(a - a0). Residual <= 2^-22 |a|.
__device__ __forceinline__ void split2_store(__half* base, size_t row,
                                             int col, const float* vv) {
    __align__(8) __half t0[4], t1[4];
    #pragma unroll
    for (int j = 0; j < 4; j++) {
        const float a = vv[j];
        t0[j] = __float2half_rn(a);
        t1[j] = __float2half_rn(a - __half2float(t0[j]));
    }
    *reinterpret_cast<uint2*>(&base[row * KW + col])       = *reinterpret_cast<uint2*>(t0);
    *reinterpret_cast<uint2*>(&base[row * KW + 512 + col]) = *reinterpret_cast<uint2*>(t1);
}
__global__ void convert_x(const float* __restrict__ x) {
    size_t i = (size_t)blockIdx.x * blockDim.x + threadIdx.x;   // one float4
    float4 v = reinterpret_cast<const float4*>(x)[i];
    size_t f = i * 4;
    float vv[4] = {v.x, v.y, v.z, v.w};
    split2_store(g_A2, f >> 9, (int)(f & 511), vv);
}
__global__ void convert_w(const float* __restrict__ w) {
    size_t i = (size_t)blockIdx.x * blockDim.x + threadIdx.x;
    float4 v = reinterpret_cast<const float4*>(w)[i];
    size_t f = i * 4;
    float vv[4] = {v.x, v.y, v.z, v.w};
    split2_store(g_B2, f >> 9, (int)(f & 511), vv);
}

// ---------------- GEMM helpers --------------------------------------------
// 3 product segments, SMALL first (chunks 0..15, fully TC-chained: |acc| ~
// 2^-11 so RZ bias ~1e-9), then a0*b0 (chunks 16..23, pair-chain + FADD).
__constant__ int2 SEG_COLS[3] = {
    {0, 512},     // a0*b1   (2^-11)
    {512, 0},     // a1*b0   (2^-11)
    {0, 0},       // a0*b0   (1) -- phase 2
};
#define NCHUNKS 24
#define SMEM_BYTES 98304

__device__ __forceinline__ void load_chunk(int c, uint32_t sAst, uint32_t sBst,
                                           int tid, int mbase, int nbase) {
    const int2 sc = SEG_COLS[c >> 3];
    const int kk = (c & 7) * 64;
    const int a_col = sc.x + kk;
    const int b_col = sc.y + kk;
    #pragma unroll
    for (int p = 0; p < 4; p++) {            // A: 128 rows x 128B
        const int o   = tid + p * 256;
        const int row = o >> 3;
        const int q   = o & 7;
        const uint32_t dst = sAst + row * 128 + ((q * 16) ^ ((row & 7) << 4));
        cp16(dst, &g_A2[(size_t)(mbase + row) * KW + a_col + q * 8]);
    }
    #pragma unroll
    for (int p = 0; p < 8; p++) {            // B: 256 rows x 128B
        const int o   = tid + p * 256;
        const int row = o >> 3;
        const int q   = o & 7;
        const uint32_t dst = sBst + row * 128 + ((q * 16) ^ ((row & 7) << 4));
        cp16(dst, &g_B2[(size_t)(nbase + row) * KW + b_col + q * 8]);
    }
    CP_COMMIT();
}

// ---------------- Kernel B: mma.sync fp16 GEMM, bias-controlled chaining ---
// CTA tile 128(m) x 256(n); 8 warps 2x4; warp tile 64x64; double-buffered.
__global__ __launch_bounds__(256, 1)
void gemm_fc1_mma(const float* __restrict__ b1) {
    extern __shared__ char smem[];
    const uint32_t sb = smem_u32(smem);
    const int tid  = threadIdx.x;
    const int lane = tid & 31;
    const int wid  = tid >> 5;
    const int wm   = wid >> 2;         // 0..1  (m)
    const int wn   = wid & 3;          // 0..3  (n)
    const int mbase = blockIdx.y * 128;
    const int nbase = blockIdx.x * 256;

    const uint32_t sA[2] = {sb, sb + 16384};
    const uint32_t sB[2] = {sb + 32768, sb + 65536};

    float acc[4][8][4];                // doubles as phase-1 TC chain registers

    const int lrow  = lane & 15;
    const int lhalf = (lane >> 4) * 16;

    load_chunk(0, sA[0], sB[0], tid, mbase, nbase);

    for (int c = 0; c < NCHUNKS; c++) {
        const int st = c & 1;
        if (c < NCHUNKS - 1) {
            load_chunk(c + 1, sA[st ^ 1], sB[st ^ 1], tid, mbase, nbase);
            CP_WAIT(1);
        } else {
            CP_WAIT(0);
        }
        __syncthreads();

        if (c < 16) {
            // Phase 1: small segments (a0b1, a1b0), fully TC-chained.
            #pragma unroll
            for (int ks = 0; ks < 4; ks++) {
                const int cb = ks * 32 + lhalf;
                uint32_t a[4][4], b[4][4];
                #pragma unroll
                for (int mm = 0; mm < 4; mm++) {
                    const int row = wm * 64 + mm * 16 + lrow;
                    ldm_x4(a[mm], sA[st] + row * 128 + (cb ^ ((row & 7) << 4)));
                }
                #pragma unroll
                for (int bq = 0; bq < 4; bq++) {
                    const int row = wn * 64 + bq * 16 + lrow;
                    ldm_x4(b[bq], sB[st] + row * 128 + (cb ^ ((row & 7) << 4)));
                }
                if (c == 0 && ks == 0) {
                    #pragma unroll
                    for (int mm = 0; mm < 4; mm++)
                        #pragma unroll
                        for (int bq = 0; bq < 4; bq++) {
                            mma_zero(acc[mm][bq * 2],     a[mm], b[bq][0], b[bq][2]);
                            mma_zero(acc[mm][bq * 2 + 1], a[mm], b[bq][1], b[bq][3]);
                        }
                } else {
                    #pragma unroll
                    for (int mm = 0; mm < 4; mm++)
                        #pragma unroll
                        for (int bq = 0; bq < 4; bq++) {
                            mma_chain(acc[mm][bq * 2],     a[mm], b[bq][0], b[bq][2]);
                            mma_chain(acc[mm][bq * 2 + 1], a[mm], b[bq][1], b[bq][3]);
                        }
                }
            }
        } else {
            // Phase 2: a0*b0. Pair-chain (k=32, |partial| small) then fold
            // with fp32 RN FADD into acc.
            #pragma unroll
            for (int kp = 0; kp < 2; kp++) {
                uint32_t a[2][4][4], b[2][4][4];
                #pragma unroll
                for (int half = 0; half < 2; half++) {
                    const int cb = (kp * 2 + half) * 32 + lhalf;
                    #pragma unroll
                    for (int mm = 0; mm < 4; mm++) {
                        const int row = wm * 64 + mm * 16 + lrow;
                        ldm_x4(a[half][mm],
                               sA[st] + row * 128 + (cb ^ ((row & 7) << 4)));
                    }
                    #pragma unroll
                    for (int bq = 0; bq < 4; bq++) {
                        const int row = wn * 64 + bq * 16 + lrow;
                        ldm_x4(b[half][bq],
                               sB[st] + row * 128 + (cb ^ ((row & 7) << 4)));
                    }
                }
                #pragma unroll
                for (int mm = 0; mm < 4; mm++)
                    #pragma unroll
                    for (int bq = 0; bq < 4; bq++) {
                        float t0[4], t1[4];
                        mma_zero (t0, a[0][mm], b[0][bq][0], b[0][bq][2]);
                        mma_chain(t0, a[1][mm], b[1][bq][0], b[1][bq][2]);
                        mma_zero (t1, a[0][mm], b[0][bq][1], b[0][bq][3]);
                        mma_chain(t1, a[1][mm], b[1][bq][1], b[1][bq][3]);
                        #pragma unroll
                        for (int e = 0; e < 4; e++) {
                            acc[mm][bq * 2][e]     += t0[e];
                            acc[mm][bq * 2 + 1][e] += t1[e];
                        }
                    }
            }
        }
        __syncthreads();
    }

    // Epilogue: bias + store f32 to g_cur.
    const int qrow = lane >> 2;            // 0..7
    const int qcol = (lane & 3) * 2;       // 0,2,4,6
    #pragma unroll
    for (int bqn = 0; bqn < 8; bqn++) {
        const int n = nbase + wn * 64 + bqn * 8 + qcol;
        const float bv0 = b1[n], bv1 = b1[n + 1];
        #pragma unroll
        for (int mm = 0; mm < 4; mm++) {
            const int r0 = mbase + wm * 64 + mm * 16 + qrow;
            float2 v0 = make_float2(acc[mm][bqn][0] + bv0, acc[mm][bqn][1] + bv1);
            float2 v1 = make_float2(acc[mm][bqn][2] + bv0, acc[mm][bqn][3] + bv1);
            *reinterpret_cast<float2*>(&g_cur[(size_t)r0 * 1024 + n])       = v0;
            *reinterpret_cast<float2*>(&g_cur[(size_t)(r0 + 8) * 1024 + n]) = v1;
        }
    }
}

// ---------------- Kernel C: LIF scan + fused output GEMM ------------------
__global__ __launch_bounds__(1024, 1)
void lif_reduce(const float* __restrict__ W2, const float* __restrict__ b2,
                float* __restrict__ out) {
    const int b = blockIdx.x;
    const int h = threadIdx.x;
    const float* p = g_cur + (size_t)b * T_STEPS * HID + h;

    float mem = 0.0f, spk_sum = 0.0f;
    #pragma unroll 4
    for (int t = 0; t < T_STEPS; t++) {
        const float c = p[t * HID];
        const float reset = (mem > 1.0f) ? 1.0f : 0.0f;
        mem = 0.9f * mem + c - reset;
        spk_sum += (mem > 1.0f) ? 1.0f : 0.0f;
    }
    float part[8];
    #pragma unroll
    for (int c = 0; c < 8; c++) part[c] = spk_sum * W2[c * HID + h];
    #pragma unroll
    for (int c = 0; c < 8; c++)
        #pragma unroll
        for (int o = 16; o > 0; o >>= 1)
            part[c] += __shfl_down_sync(0xffffffffu, part[c], o);

    __shared__ float s_red[8][32];
    const int lane = h & 31, warp = h >> 5;
    if (lane == 0)
        #pragma unroll
        for (int c = 0; c < 8; c++) s_red[c][warp] = part[c];
    __syncthreads();
    if (threadIdx.x < 256) {
        const int c = threadIdx.x >> 5, w = threadIdx.x & 31;
        float v = s_red[c][w];
        #pragma unroll
        for (int o = 16; o > 0; o >>= 1)
            v += __shfl_down_sync(0xffffffffu, v, o);
        if (w == 0) out[b * CLS + c] = v + 100.0f * b2[c];
    }
}

// ---------------------------------------------------------------------------
extern "C" void kernel_launch(void* const* d_in, const int* in_sizes, int n_in,
                              void* d_out, int out_size) {
    const float* x  = (const float*)d_in[0];
    const float* W1 = (const float*)d_in[1];
    const float* b1 = (const float*)d_in[2];
    const float* W2 = (const float*)d_in[3];
    const float* b2 = (const float*)d_in[4];
    float* out = (float*)d_out;

    cudaFuncSetAttribute(gemm_fc1_mma, cudaFuncAttributeMaxDynamicSharedMemorySize,
                         SMEM_BYTES);

    convert_x<<<(M_TOTAL * IN_F / 4) / 256, 256>>>(x);   // 12800 blocks
    convert_w<<<(HID * IN_F / 4) / 256, 256>>>(W1);      // 512 blocks
    // grid: x = n-blocks (4) fastest -> CTAs sharing an A chunk co-scheduled
    gemm_fc1_mma<<<dim3(HID / 256, M_TOTAL / 128), 256, SMEM_BYTES>>>(b1);
    lif_reduce<<<B_SZ, 1024>>>(W2, b2, out);
}

// round 10
// speedup vs baseline: 6.8223x; 1.2282x over previous
#include <cuda_runtime.h>
#include <cuda_fp16.h>
#include <cstdint>

// Shapes: x[256,100,512] f32, W1[1024,512] f32, b1[1024], W2[8,1024], b2[8]
// out[256,8] f32.
#define T_STEPS 100
#define B_SZ    256
#define IN_F    512
#define HID     1024
#define CLS     8
#define M_TOTAL (B_SZ * T_STEPS)   // 25600
#define KW      1024               // 2 fp16 terms x 512

// ---------------- device scratch (static; no allocations) -----------------
__device__ float  g_cur[(size_t)M_TOTAL * HID];   // 104.9 MB
__device__ __half g_A2[(size_t)M_TOTAL * KW];     // [m][a0|a1] 52.4 MB
__device__ __half g_B2[(size_t)HID * KW];         // [n][b0|b1]  2.1 MB

// ---------------- base-PTX helpers (sm_80+) --------------------------------
__device__ __forceinline__ uint32_t smem_u32(const void* p) {
    uint32_t a;
    asm("{ .reg .u64 t; cvta.to.shared.u64 t, %1; cvt.u32.u64 %0, t; }" : "=r"(a) : "l"(p));
    return a;
}
__device__ __forceinline__ void cp16(uint32_t dst, const void* src) {
    asm volatile("cp.async.cg.shared.global [%0], [%1], 16;" :: "r"(dst), "l"(src));
}
#define CP_COMMIT() asm volatile("cp.async.commit_group;")
#define CP_WAIT(n)  asm volatile("cp.async.wait_group %0;" :: "n"(n))

__device__ __forceinline__ void ldm_x4(uint32_t* r, uint32_t addr) {
    asm volatile("ldmatrix.sync.aligned.m8n8.x4.shared.b16 {%0,%1,%2,%3}, [%4];"
        : "=r"(r[0]), "=r"(r[1]), "=r"(r[2]), "=r"(r[3]) : "r"(addr));
}
// Chained mma: D += A*B through the TC accumulator (RZ-biased add; safe only
// while |acc| stays ~2^-11 -- phase-1 segments).
__device__ __forceinline__ void mma_chain(float* c, const uint32_t* a,
                                          uint32_t b0, uint32_t b1) {
    asm volatile("mma.sync.aligned.m16n8k16.row.col.f32.f16.f16.f32 "
        "{%0,%1,%2,%3}, {%4,%5,%6,%7}, {%8,%9}, {%0,%1,%2,%3};"
        : "+f"(c[0]), "+f"(c[1]), "+f"(c[2]), "+f"(c[3])
        : "r"(a[0]), "r"(a[1]), "r"(a[2]), "r"(a[3]), "r"(b0), "r"(b1));
}
// Isolated dot: D = A*B + 0 (exact, bias-free) -- phase-2 a0*b0.
__device__ __forceinline__ void mma_zero(float* d, const uint32_t* a,
                                         uint32_t b0, uint32_t b1) {
    asm volatile("mma.sync.aligned.m16n8k16.row.col.f32.f16.f16.f32 "
        "{%0,%1,%2,%3}, {%4,%5,%6,%7}, {%8,%9}, {%10,%10,%10,%10};"
        : "=f"(d[0]), "=f"(d[1]), "=f"(d[2]), "=f"(d[3])
        : "r"(a[0]), "r"(a[1]), "r"(a[2]), "r"(a[3]), "r"(b0), "r"(b1),
          "f"(0.0f));
}

// ---------------- Kernel A: fp32 -> 2-way fp16 split (x and W fused) -------
__device__ __forceinline__ void split2_store(__half* base, size_t row,
                                             int col, const float* vv) {
    __align__(8) __half t0[4], t1[4];
    #pragma unroll
    for (int j = 0; j < 4; j++) {
        const float a = vv[j];
        t0[j] = __float2half_rn(a);
        t1[j] = __float2half_rn(a - __half2float(t0[j]));
    }
    *reinterpret_cast<uint2*>(&base[row * KW + col])       = *reinterpret_cast<uint2*>(t0);
    *reinterpret_cast<uint2*>(&base[row * KW + 512 + col]) = *reinterpret_cast<uint2*>(t1);
}
#define X_BLOCKS ((M_TOTAL * IN_F / 4) / 256)    // 12800
#define W_BLOCKS ((HID * IN_F / 4) / 256)        // 512
__global__ void convert_xw(const float* __restrict__ x, const float* __restrict__ w) {
    if (blockIdx.x < X_BLOCKS) {
        size_t i = (size_t)blockIdx.x * blockDim.x + threadIdx.x;
        float4 v = reinterpret_cast<const float4*>(x)[i];
        size_t f = i * 4;
        float vv[4] = {v.x, v.y, v.z, v.w};
        split2_store(g_A2, f >> 9, (int)(f & 511), vv);
    } else {
        size_t i = (size_t)(blockIdx.x - X_BLOCKS) * blockDim.x + threadIdx.x;
        float4 v = reinterpret_cast<const float4*>(w)[i];
        size_t f = i * 4;
        float vv[4] = {v.x, v.y, v.z, v.w};
        split2_store(g_B2, f >> 9, (int)(f & 511), vv);
    }
}

// ---------------- GEMM helpers --------------------------------------------
// 3 product segments, SMALL first (chunks 0..15, fully TC-chained: |acc| ~
// 2^-11 so RZ bias ~1e-9), then a0*b0 (chunks 16..23, isolated mma + FADD).
__constant__ int2 SEG_COLS[3] = {
    {0, 512},     // a0*b1   (2^-11)
    {512, 0},     // a1*b0   (2^-11)
    {0, 0},       // a0*b0   (1) -- phase 2
};
#define NCHUNKS 24
#define SMEM_BYTES 65536

__device__ __forceinline__ void load_chunk(int c, uint32_t sAst, uint32_t sBst,
                                           int tid, int mbase, int nbase) {
    const int2 sc = SEG_COLS[c >> 3];
    const int kk = (c & 7) * 64;
    const int a_col = sc.x + kk;
    const int b_col = sc.y + kk;
    #pragma unroll
    for (int p = 0; p < 4; p++) {            // A: 128 rows x 128B
        const int o   = tid + p * 256;
        const int row = o >> 3;
        const int q   = o & 7;
        const uint32_t dst = sAst + row * 128 + ((q * 16) ^ ((row & 7) << 4));
        cp16(dst, &g_A2[(size_t)(mbase + row) * KW + a_col + q * 8]);
    }
    #pragma unroll
    for (int p = 0; p < 4; p++) {            // B: 128 rows x 128B
        const int o   = tid + p * 256;
        const int row = o >> 3;
        const int q   = o & 7;
        const uint32_t dst = sBst + row * 128 + ((q * 16) ^ ((row & 7) << 4));
        cp16(dst, &g_B2[(size_t)(nbase + row) * KW + b_col + q * 8]);
    }
    CP_COMMIT();
}

// ---------------- Kernel B: fp16 mma GEMM, 128x128 tile, occupancy 2 -------
// 8 warps in 2(m) x 4(n); warp tile 64(m) x 32(n); double-buffered cp.async.
// Grid 1600 CTAs (vs 800) + 2 CTAs/SM: tail waste 11% -> ~2%, and the
// co-resident CTA fills barrier/CP_WAIT gaps in the tensor pipe.
__global__ __launch_bounds__(256, 2)
void gemm_fc1_mma(const float* __restrict__ b1) {
    extern __shared__ char smem[];
    const uint32_t sb = smem_u32(smem);
    const int tid  = threadIdx.x;
    const int lane = tid & 31;
    const int wid  = tid >> 5;
    const int wm   = wid >> 2;         // 0..1  (m)
    const int wn   = wid & 3;          // 0..3  (n)
    const int mbase = blockIdx.y * 128;
    const int nbase = blockIdx.x * 128;

    const uint32_t sA[2] = {sb, sb + 16384};
    const uint32_t sB[2] = {sb + 32768, sb + 49152};

    float acc[4][4][4];                // [mm][n8 blk][e] = 64 regs

    const int lrow  = lane & 15;
    const int lhalf = (lane >> 4) * 16;

    load_chunk(0, sA[0], sB[0], tid, mbase, nbase);

    for (int c = 0; c < NCHUNKS; c++) {
        const int st = c & 1;
        if (c < NCHUNKS - 1) {
            load_chunk(c + 1, sA[st ^ 1], sB[st ^ 1], tid, mbase, nbase);
            CP_WAIT(1);
        } else {
            CP_WAIT(0);
        }
        __syncthreads();

        #pragma unroll
        for (int ks = 0; ks < 4; ks++) {
            const int cb = ks * 32 + lhalf;
            uint32_t a[4][4], b[2][4];
            #pragma unroll
            for (int mm = 0; mm < 4; mm++) {
                const int row = wm * 64 + mm * 16 + lrow;
                ldm_x4(a[mm], sA[st] + row * 128 + (cb ^ ((row & 7) << 4)));
            }
            #pragma unroll
            for (int bq = 0; bq < 2; bq++) {
                const int row = wn * 32 + bq * 16 + lrow;
                ldm_x4(b[bq], sB[st] + row * 128 + (cb ^ ((row & 7) << 4)));
            }
            if (c == 0 && ks == 0) {
                // phase-1 start: initialize the TC chain
                #pragma unroll
                for (int mm = 0; mm < 4; mm++)
                    #pragma unroll
                    for (int bq = 0; bq < 2; bq++) {
                        mma_zero(acc[mm][bq * 2],     a[mm], b[bq][0], b[bq][2]);
                        mma_zero(acc[mm][bq * 2 + 1], a[mm], b[bq][1], b[bq][3]);
                    }
            } else if (c < 16) {
                // phase 1: small segments, fully TC-chained (bias ~1e-9)
                #pragma unroll
                for (int mm = 0; mm < 4; mm++)
                    #pragma unroll
                    for (int bq = 0; bq < 2; bq++) {
                        mma_chain(acc[mm][bq * 2],     a[mm], b[bq][0], b[bq][2]);
                        mma_chain(acc[mm][bq * 2 + 1], a[mm], b[bq][1], b[bq][3]);
                    }
            } else {
                // phase 2: a0*b0 -- isolated k16 dots + fp32 RN folds
                #pragma unroll
                for (int mm = 0; mm < 4; mm++)
                    #pragma unroll
                    for (int bq = 0; bq < 2; bq++) {
                        float t0[4], t1[4];
                        mma_zero(t0, a[mm], b[bq][0], b[bq][2]);
                        mma_zero(t1, a[mm], b[bq][1], b[bq][3]);
                        #pragma unroll
                        for (int e = 0; e < 4; e++) {
                            acc[mm][bq * 2][e]     += t0[e];
                            acc[mm][bq * 2 + 1][e] += t1[e];
                        }
                    }
            }
        }
        __syncthreads();
    }

    // Epilogue: bias + store f32 to g_cur.
    const int qrow = lane >> 2;            // 0..7
    const int qcol = (lane & 3) * 2;       // 0,2,4,6
    #pragma unroll
    for (int nb = 0; nb < 4; nb++) {
        const int n = nbase + wn * 32 + nb * 8 + qcol;
        const float bv0 = b1[n], bv1 = b1[n + 1];
        #pragma unroll
        for (int mm = 0; mm < 4; mm++) {
            const int r0 = mbase + wm * 64 + mm * 16 + qrow;
            float2 v0 = make_float2(acc[mm][nb][0] + bv0, acc[mm][nb][1] + bv1);
            float2 v1 = make_float2(acc[mm][nb][2] + bv0, acc[mm][nb][3] + bv1);
            *reinterpret_cast<float2*>(&g_cur[(size_t)r0 * 1024 + n])       = v0;
            *reinterpret_cast<float2*>(&g_cur[(size_t)(r0 + 8) * 1024 + n]) = v1;
        }
    }
}

// ---------------- Kernel C: LIF scan + fused output GEMM ------------------
__global__ __launch_bounds__(1024, 1)
void lif_reduce(const float* __restrict__ W2, const float* __restrict__ b2,
                float* __restrict__ out) {
    const int b = blockIdx.x;
    const int h = threadIdx.x;
    const float* p = g_cur + (size_t)b * T_STEPS * HID + h;

    float mem = 0.0f, spk_sum = 0.0f;
    #pragma unroll 4
    for (int t = 0; t < T_STEPS; t++) {
        const float c = p[t * HID];
        const float reset = (mem > 1.0f) ? 1.0f : 0.0f;
        mem = 0.9f * mem + c - reset;
        spk_sum += (mem > 1.0f) ? 1.0f : 0.0f;
    }
    float part[8];
    #pragma unroll
    for (int c = 0; c < 8; c++) part[c] = spk_sum * W2[c * HID + h];
    #pragma unroll
    for (int c = 0; c < 8; c++)
        #pragma unroll
        for (int o = 16; o > 0; o >>= 1)
            part[c] += __shfl_down_sync(0xffffffffu, part[c], o);

    __shared__ float s_red[8][32];
    const int lane = h & 31, warp = h >> 5;
    if (lane == 0)
        #pragma unroll
        for (int c = 0; c < 8; c++) s_red[c][warp] = part[c];
    __syncthreads();
    if (threadIdx.x < 256) {
        const int c = threadIdx.x >> 5, w = threadIdx.x & 31;
        float v = s_red[c][w];
        #pragma unroll
        for (int o = 16; o > 0; o >>= 1)
            v += __shfl_down_sync(0xffffffffu, v, o);
        if (w == 0) out[b * CLS + c] = v + 100.0f * b2[c];
    }
}

// ---------------------------------------------------------------------------
extern "C" void kernel_launch(void* const* d_in, const int* in_sizes, int n_in,
                              void* d_out, int out_size) {
    const float* x  = (const float*)d_in[0];
    const float* W1 = (const float*)d_in[1];
    const float* b1 = (const float*)d_in[2];
    const float* W2 = (const float*)d_in[3];
    const float* b2 = (const float*)d_in[4];
    float* out = (float*)d_out;

    cudaFuncSetAttribute(gemm_fc1_mma, cudaFuncAttributeMaxDynamicSharedMemorySize,
                         SMEM_BYTES);

    convert_xw<<<X_BLOCKS + W_BLOCKS, 256>>>(x, W1);
    // grid: x = n-tiles (8) fastest -> CTAs sharing an A chunk co-scheduled
    gemm_fc1_mma<<<dim3(HID / 128, M_TOTAL / 128), 256, SMEM_BYTES>>>(b1);
    lif_reduce<<<B_SZ, 1024>>>(W2, b2, out);
}